// round 16
// baseline (speedup 1.0000x reference)
#include <cuda_runtime.h>
#include <cstdint>

#define GRIDX 128
#define NTH   512
#define BB    128
#define SS    512
#define II    128
#define HH    512

// ---------------- persistent device state (no allocations allowed) -------------
static __device__ __align__(16) float g_xT[(size_t)SS*II*BB];   // [t][i][b]
static __device__ __align__(16) float g_h0T[2][HH*BB];          // [u][b]
static __device__ __align__(16) float g_h1T[2][HH*BB];
static __device__ __align__(16) float g_decT[II*BB];            // [i][b]
static __device__ unsigned g_arrive = 0;
static __device__ unsigned g_release = 0;

__device__ __forceinline__ float sigf(float x){ return 1.0f/(1.0f+__expf(-x)); }
__device__ __forceinline__ float tanhf_(float x){ return 1.0f - 2.0f/(__expf(2.0f*x)+1.0f); }

// ---- packed f32x2 (dual-rate fp32; proven) ----
typedef unsigned long long ull;
#define PACK2(d,lo,hi) asm("mov.b64 %0,{%1,%2};" : "=l"(d) : "f"(lo),"f"(hi))
#define FMA2(d,a,b)    asm("fma.rn.f32x2 %0,%1,%2,%0;" : "+l"(d) : "l"(a),"l"(b))

// ---- cp.async (per-thread commit groups; PRIVATE ring per warp) ----
#define CPA16(d,s) asm volatile("cp.async.cg.shared.global [%0],[%1],16;" :: "r"(d),"l"(s))
#define CPC()      asm volatile("cp.async.commit_group;")
#define CPW(n)     asm volatile("cp.async.wait_group %0;" :: "n"(n))
#define SYNCWARP() asm volatile("bar.warp.sync 0xFFFFFFFF;" ::: "memory")

// software grid barrier: 128 co-resident CTAs (1 CTA/SM via ~207KB smem)
__device__ __forceinline__ void grid_sync(unsigned base, unsigned target)
{
    __syncthreads();
    if (threadIdx.x == 0) {
        __threadfence();
        unsigned arrived = atomicAdd(&g_arrive, 1u);
        if (arrived == GRIDX - 1u) {
            g_arrive = 0u;
            __threadfence();
            atomicAdd(&g_release, 1u);
        } else {
            volatile unsigned* rel = &g_release;
            while ((*rel - base) < target) { __nanosleep(32); }
        }
        __threadfence();
    }
    __syncthreads();
}

// Weights -> SMEM as Wc[k][16]; col c = unit*4+gate, global row R = gate*H+u0+unit.
__device__ void load_layer_weights(float* Wc, float* bias, int lenA,
                                   const float* __restrict__ W_ih,
                                   const float* __restrict__ W_hh,
                                   const float* __restrict__ b_ih,
                                   const float* __restrict__ b_hh, int u0)
{
    const int tid = threadIdx.x;
    const int K = lenA + HH;
    for (int idx = tid; idx < K * 16; idx += NTH) {
        int k  = idx >> 4;
        int c  = idx & 15;
        int j  = c >> 2;
        int gt = c & 3;
        int R  = gt * HH + u0 + j;
        Wc[idx] = (k < lenA) ? W_ih[R * lenA + k] : W_hh[R * HH + (k - lenA)];
    }
    if (tid < 16) {
        int j = tid >> 2, gt = tid & 3;
        int R = gt * HH + u0 + j;
        bias[tid] = b_ih[R] + b_hh[R];
    }
}

// stage one 8-row x 256B act half-panel into private ring slot (4 CPA16/thread)
__device__ __forceinline__ void stage_group(uint32_t dst, const float* __restrict__ srcRow0,
                                            int l, int bhOff)
{
#pragma unroll
    for (int q = 0; q < 4; q++) {
        int idx = l + 32 * q;                 // 0..127 chunks of 16B
        int row = idx >> 4, off = (idx & 15) * 16;
        CPA16(dst + (uint32_t)(row * 256 + off),
              (const char*)(srcRow0 + (size_t)row * BB + bhOff) + off);
    }
    CPC();
}

// One LSTM layer step: 16 warps = 8 k-slices x 2 batch-halves.
// Warp w: ws = w&7 owns k in [ws*K/8,(ws+1)*K/8), bh = w>>3 owns batches bh*64..+64.
// Lane l: bq = l>>1 (4 batches), gg = l&1 (8 cols as 4 f32x2 col-pairs).
// acc[batch 0..3][colpair 0..3]: weights load as NATURAL f32x2 pairs (no PACK2);
// acts packed [a,a] with 4 PACK2 per k.
__device__ void lstm_step(const float* __restrict__ srcA, int lenA,
                          const float* __restrict__ srcB,
                          const float* __restrict__ Wc, const float* __restrict__ bias_s,
                          ull* __restrict__ red, float* __restrict__ ringw, uint32_t ringw_u32,
                          float* __restrict__ hOut, float& c_st, int ub)
{
    const int tid = threadIdx.x;
    const int w = tid >> 5, l = tid & 31;
    const int ws = w & 7, bh = w >> 3;
    const int bq = l >> 1, gg = l & 1;
    const int bhOff = bh * 64;                 // float offset into each 128-b row
    const int K = lenA + HH;
    const int kper = K >> 3;
    const int k0 = ws * kper, k1 = k0 + kper;

    ull acc[4][4];
#pragma unroll
    for (int bp = 0; bp < 4; bp++)
#pragma unroll
        for (int cp = 0; cp < 4; cp++) { float z = 0.0f; PACK2(acc[bp][cp], z, z); }

#define FMAK(av, KK)                                                             \
    do {                                                                         \
        const ulonglong2* wp = (const ulonglong2*)(Wc + (KK) * 16 + gg * 8);     \
        ulonglong2 Wa = wp[0], Wb = wp[1];                                       \
        ull A0, A1, A2, A3;                                                      \
        PACK2(A0, (av).x, (av).x); PACK2(A1, (av).y, (av).y);                    \
        PACK2(A2, (av).z, (av).z); PACK2(A3, (av).w, (av).w);                    \
        FMA2(acc[0][0], A0, Wa.x); FMA2(acc[0][1], A0, Wa.y);                    \
        FMA2(acc[0][2], A0, Wb.x); FMA2(acc[0][3], A0, Wb.y);                    \
        FMA2(acc[1][0], A1, Wa.x); FMA2(acc[1][1], A1, Wa.y);                    \
        FMA2(acc[1][2], A1, Wb.x); FMA2(acc[1][3], A1, Wb.y);                    \
        FMA2(acc[2][0], A2, Wa.x); FMA2(acc[2][1], A2, Wa.y);                    \
        FMA2(acc[2][2], A2, Wb.x); FMA2(acc[2][3], A2, Wb.y);                    \
        FMA2(acc[3][0], A3, Wa.x); FMA2(acc[3][1], A3, Wa.y);                    \
        FMA2(acc[3][2], A3, Wb.x); FMA2(acc[3][3], A3, Wb.y);                    \
    } while (0)

    // cp.async-pipelined segment: 8-row groups, private 3-slot ring, prefetch 2.
    // (S1-S0) divisible by 8 for every warp slice in this problem.
#define SEGLOOP(BASE, OFS, S0, S1)                                               \
    do {                                                                         \
        int s0 = (S0), s1 = (S1);                                                \
        if (s1 > s0) {                                                           \
            const float* bp_ = (BASE) - (size_t)(OFS) * BB;                      \
            const int ng = (s1 - s0) >> 3;                                       \
            stage_group(ringw_u32, bp_ + (size_t)s0 * BB, l, bhOff);             \
            if (ng > 1) stage_group(ringw_u32 + 2048u, bp_ + (size_t)(s0 + 8) * BB, l, bhOff); \
            for (int g = 0; g < ng; g++) {                                       \
                if (g + 2 < ng) {                                                \
                    int slot = (g + 2) % 3;                                      \
                    stage_group(ringw_u32 + (uint32_t)slot * 2048u,              \
                                bp_ + (size_t)(s0 + (g + 2) * 8) * BB, l, bhOff);\
                    CPW(2);                                                      \
                } else if (g + 1 < ng) {                                         \
                    CPW(1);                                                      \
                } else {                                                         \
                    CPW(0);                                                      \
                }                                                                \
                SYNCWARP();                                                      \
                const float* sl = ringw + (size_t)(g % 3) * 512 + bq * 4;        \
                _Pragma("unroll")                                                \
                for (int r = 0; r < 8; r++) {                                    \
                    float4 av = *(const float4*)(sl + r * 64);                   \
                    FMAK(av, s0 + g * 8 + r);                                    \
                }                                                                \
                SYNCWARP();                                                      \
            }                                                                    \
        }                                                                        \
    } while (0)

    // segment A: k in [k0,k1) ∩ [0,lenA); segment B: k in [k0,k1) ∩ [lenA,K)
    SEGLOOP(srcA, 0, k0, (k1 < lenA ? k1 : lenA));
    SEGLOOP(srcB, lenA, (k0 > lenA ? k0 : lenA), k1);
#undef SEGLOOP
#undef FMAK

    // red ALIASES the ring: all warps must drain their rings first
    __syncthreads();

    // split-K-8 reduction (per batch-half): red[(w*32+l)*17 + bp*4+cp] (ull, padded)
    {
        ull* rp = red + (size_t)(w * 32 + l) * 17;
#pragma unroll
        for (int bp = 0; bp < 4; bp++)
#pragma unroll
            for (int cp = 0; cp < 4; cp++)
                rp[bp * 4 + cp] = acc[bp][cp];
    }
    __syncthreads();

    // gather + cell update: thread t = (ul = t>>7, b = t&127), one cell each
    const float* redf = (const float*)red;
    const int b = tid & 127;
    const int ul = tid >> 7;
    const int bhg = b >> 6, bb = b & 63;
    const int bqg = bb >> 2, bpg = bb & 3;
    float g4[4];
#pragma unroll
    for (int gt = 0; gt < 4; gt++) {
        const int c = ul * 4 + gt;
        const int ggc = c >> 3, cpg = (c & 7) >> 1, half = c & 1;
        const int lane = bqg * 2 + ggc;
        float s = bias_s[c];
#pragma unroll
        for (int ws2 = 0; ws2 < 8; ws2++) {
            int w2 = bhg * 8 + ws2;
            s += redf[(((size_t)(w2 * 32 + lane) * 17 + bpg * 4 + cpg) << 1) + half];
        }
        g4[gt] = s;
    }
    float cn = sigf(g4[1]) * c_st + sigf(g4[0]) * tanhf_(g4[2]);
    c_st = cn;
    hOut[(size_t)(ub + ul) * BB + b] = sigf(g4[3]) * tanhf_(cn);
    __syncthreads();
}

// pred[b, icol] = h1[b,:] . wlin (h1 transposed [u][b]); 512 threads, 4-way split-K
__device__ void pred_step(const float* __restrict__ h1T, const float* __restrict__ wlin_s,
                          float* __restrict__ redf,
                          int t, float* __restrict__ out, int icol)
{
    const int tid = threadIdx.x;
    const int b = tid >> 2, q = tid & 3;
    const float* hp = h1T + (size_t)(q * 128) * BB + b;
    const float* wl = wlin_s + q * 128;
    float acc = 0.0f;
#pragma unroll 8
    for (int u = 0; u < 128; u++)
        acc += hp[(size_t)u * BB] * wl[u];
    __syncthreads();
    if (q) redf[(q - 1) * 128 + b] = acc;
    __syncthreads();
    if (!q) {
        float pr = acc + redf[b] + redf[128 + b] + redf[256 + b];
        out[((size_t)b * SS + t) * II + icol] = pr;
        g_decT[icol * BB + b] = pr;
    }
    __syncthreads();
}

// x[b][t][i] -> xT[t][i][b]
__global__ void transpose_x(const float* __restrict__ x)
{
    __shared__ float tile[32][33];
    int t = blockIdx.x;
    int i0 = blockIdx.y * 32, b0 = blockIdx.z * 32;
    int tx = threadIdx.x, ty = threadIdx.y;
#pragma unroll
    for (int j = 0; j < 32; j += 8)
        tile[ty + j][tx] = x[((size_t)(b0 + ty + j) * SS + t) * II + i0 + tx];
    __syncthreads();
#pragma unroll
    for (int j = 0; j < 32; j += 8)
        g_xT[((size_t)t * II + i0 + ty + j) * BB + b0 + tx] = tile[tx][ty + j];
}

__global__ void __launch_bounds__(NTH, 1)
lstm_ae_kernel(const float* Wih_en0, const float* Whh_en0, const float* bih_en0, const float* bhh_en0,
               const float* Wih_en1, const float* Whh_en1, const float* bih_en1, const float* bhh_en1,
               const float* Wih_de0, const float* Whh_de0, const float* bih_de0, const float* bhh_de0,
               const float* Wih_de1, const float* Whh_de1, const float* bih_de1, const float* bhh_de1,
               const float* Wlin,
               float* __restrict__ out)
{
    extern __shared__ float sm[];
    float* Wc1    = sm;                        // 16384 f32 (K=1024 layer)
    float* Wc0    = Wc1 + 16384;               // 10240 f32 (K=640 layer)
    float* ring   = Wc0 + 10240;               // 16 warps * 3 slots * 512 f32 = 96KB
    ull*   red    = (ull*)ring;                // ALIASED (512*17 ull = 68KB < 96KB)
    float* wlin_s = ring + 24576;              // 512
    float* bias0  = wlin_s + 512;              // 16
    float* bias1  = bias0 + 16;                // 16

    const int tid = threadIdx.x;
    const int u0  = blockIdx.x * 4;
    const int w   = tid >> 5;

    float* ringw = ring + (size_t)w * 1536;    // private 3 x 512-f32 slots
    uint32_t ringw_u32;
    {
        uint32_t b32;
        asm("{ .reg .u64 t; cvta.to.shared.u64 t, %1; cvt.u32.u64 %0, t; }" : "=r"(b32) : "l"(ringw));
        ringw_u32 = b32;
    }

    __shared__ unsigned s_base;
    if (tid == 0) s_base = atomicAdd(&g_release, 0u);

    // zero initial states + decoder feedback
    {
        int g = blockIdx.x * NTH + tid;        // 0..65535
        g_h0T[0][g] = 0.0f; g_h1T[0][g] = 0.0f;
        if (g < II * BB) g_decT[g] = 0.0f;
    }

    load_layer_weights(Wc0, bias0, II, Wih_en0, Whh_en0, bih_en0, bhh_en0, u0);
    load_layer_weights(Wc1, bias1, HH, Wih_en1, Whh_en1, bih_en1, bhh_en1, u0);
    __syncthreads();

    unsigned base = s_base;
    unsigned nsync = 0;
    grid_sync(base, ++nsync);

    float c0 = 0.0f, c1 = 0.0f;   // one (unit,batch) cell state per thread

    int p = 0;
    // ---- encoder ----
    for (int t = 0; t < SS; t++) {
        lstm_step(g_xT + (size_t)t * II * BB, II, g_h0T[p],
                  Wc0, bias0, red, ringw, ringw_u32, g_h0T[p ^ 1], c0, u0);
        grid_sync(base, ++nsync);
        lstm_step(g_h0T[p ^ 1], HH, g_h1T[p],
                  Wc1, bias1, red, ringw, ringw_u32, g_h1T[p ^ 1], c1, u0);
        grid_sync(base, ++nsync);
        p ^= 1;
    }

    // ---- swap to decoder weights ----
    load_layer_weights(Wc0, bias0, II, Wih_de0, Whh_de0, bih_de0, bhh_de0, u0);
    load_layer_weights(Wc1, bias1, HH, Wih_de1, Whh_de1, bih_de1, bhh_de1, u0);
    for (int k = tid; k < HH; k += NTH) wlin_s[k] = Wlin[blockIdx.x * HH + k];
    __syncthreads();

    // ---- decoder (closed loop) ----
    for (int t = 0; t < SS; t++) {
        lstm_step(g_decT, II, g_h0T[p],
                  Wc0, bias0, red, ringw, ringw_u32, g_h0T[p ^ 1], c0, u0);
        grid_sync(base, ++nsync);
        lstm_step(g_h0T[p ^ 1], HH, g_h1T[p],
                  Wc1, bias1, red, ringw, ringw_u32, g_h1T[p ^ 1], c1, u0);
        grid_sync(base, ++nsync);
        pred_step(g_h1T[p ^ 1], wlin_s, (float*)red, t, out, blockIdx.x);
        grid_sync(base, ++nsync);
        p ^= 1;
    }
}

extern "C" void kernel_launch(void* const* d_in, const int* in_sizes, int n_in,
                              void* d_out, int out_size)
{
    const float* p[18];
    for (int i = 0; i < 18; i++) p[i] = (const float*)d_in[i];

    transpose_x<<<dim3(SS, II / 32, BB / 32), dim3(32, 8)>>>(p[0]);

    // (16384 + 10240 + 24576 + 512 + 16 + 16) * 4 = 206976 B
    const size_t shmem = (16384 + 10240 + 24576 + 512 + 16 + 16) * sizeof(float);
    cudaFuncSetAttribute(lstm_ae_kernel, cudaFuncAttributeMaxDynamicSharedMemorySize, (int)shmem);

    lstm_ae_kernel<<<GRIDX, NTH, shmem>>>(
        p[1], p[2], p[3], p[4],
        p[5], p[6], p[7], p[8],
        p[9], p[10], p[11], p[12],
        p[13], p[14], p[15], p[16],
        p[17],
        (float*)d_out);
}

// round 17
// speedup vs baseline: 1.0403x; 1.0403x over previous
#include <cuda_runtime.h>
#include <cstdint>

#define GRIDX 128
#define NTH   512
#define BB    128
#define SS    512
#define II    128
#define HH    512

// ---------------- persistent device state (no allocations allowed) -------------
static __device__ __align__(16) float g_xT[(size_t)SS*II*BB];   // [t][i][b]
static __device__ __align__(16) float g_h0T[2][HH*BB];          // [u][b]
static __device__ __align__(16) float g_h1T[2][HH*BB];
static __device__ __align__(16) float g_decT[II*BB];            // [i][b]
static __device__ unsigned g_arrive = 0;
static __device__ unsigned g_release = 0;

__device__ __forceinline__ float sigf(float x){ return 1.0f/(1.0f+__expf(-x)); }
__device__ __forceinline__ float tanhf_(float x){ return 1.0f - 2.0f/(__expf(2.0f*x)+1.0f); }

// ---- packed f32x2 (dual-rate fp32; proven) ----
typedef unsigned long long ull;
#define PACK2(d,lo,hi) asm("mov.b64 %0,{%1,%2};" : "=l"(d) : "f"(lo),"f"(hi))
#define FMA2(d,a,b)    asm("fma.rn.f32x2 %0,%1,%2,%0;" : "+l"(d) : "l"(a),"l"(b))

// ---- cp.async (per-thread commit groups; PRIVATE ring per warp) ----
#define CPA16(d,s) asm volatile("cp.async.cg.shared.global [%0],[%1],16;" :: "r"(d),"l"(s))
#define CPC()      asm volatile("cp.async.commit_group;")
#define CPW(n)     asm volatile("cp.async.wait_group %0;" :: "n"(n))
#define SYNCWARP() asm volatile("bar.warp.sync 0xFFFFFFFF;" ::: "memory")

// ---- split grid barrier (128 co-resident CTAs; 1 CTA/SM via ~222KB smem) ------
__device__ __forceinline__ void arrive_grid()
{
    __syncthreads();                         // all CTA threads' writes done
    if (threadIdx.x == 0) {
        __threadfence();                     // publish
        unsigned a = atomicAdd(&g_arrive, 1u);
        if (a == GRIDX - 1u) {
            g_arrive = 0u;
            __threadfence();
            atomicAdd(&g_release, 1u);
        }
    }
}
__device__ __forceinline__ void wait_grid(unsigned base, unsigned target)
{
    if (threadIdx.x == 0) {
        volatile unsigned* rel = &g_release;
        while ((*rel - base) < target) { __nanosleep(32); }
        __threadfence();                     // acquire (L1 invalidate)
    }
    __syncthreads();
}

// Weights -> SMEM as Wc[k][16]; col c = unit*4+gate, global row R = gate*H+u0+unit.
__device__ void load_layer_weights(float* Wc, float* bias, int lenA,
                                   const float* __restrict__ W_ih,
                                   const float* __restrict__ W_hh,
                                   const float* __restrict__ b_ih,
                                   const float* __restrict__ b_hh, int u0)
{
    const int tid = threadIdx.x;
    const int K = lenA + HH;
    for (int idx = tid; idx < K * 16; idx += NTH) {
        int k  = idx >> 4;
        int c  = idx & 15;
        int j  = c >> 2;
        int gt = c & 3;
        int R  = gt * HH + u0 + j;
        Wc[idx] = (k < lenA) ? W_ih[R * lenA + k] : W_hh[R * HH + (k - lenA)];
    }
    if (tid < 16) {
        int j = tid >> 2, gt = tid & 3;
        int R = gt * HH + u0 + j;
        bias[tid] = b_ih[R] + b_hh[R];
    }
}

// stage one 4-row x 256B act half-panel into private ring slot (2 CPA16/thread)
__device__ __forceinline__ void stage_group(uint32_t dst, const float* __restrict__ srcRow0,
                                            int l, int bhOff)
{
#pragma unroll
    for (int q = 0; q < 2; q++) {
        int idx = l + 32 * q;                 // 0..63 chunks of 16B
        int row = idx >> 4, off = (idx & 15) * 16;
        CPA16(dst + (uint32_t)(row * 256 + off),
              (const char*)(srcRow0 + (size_t)row * BB + bhOff) + off);
    }
    CPC();
}

// One LSTM layer step: 16 warps = 8 k-slices x 2 batch-halves (R15 tile).
// Sources: seg0 (ready) computed first, wait_grid, then seg1 (pending).
// Warp w: ws = w&7 takes slice [ws*len/8,+len/8) of EACH segment; bh = w>>3.
// Lane l: bq = l>>1 (2 batch-pairs), gg = l&1 (8 cols). acc[2][8] f32x2 (batch pairs).
__device__ void lstm_step(const float* __restrict__ s0, int kb0, int len0,
                          const float* __restrict__ s1, int kb1, int len1,
                          const float* __restrict__ Wc, const float* __restrict__ bias_s,
                          ull* __restrict__ red, float* __restrict__ ringw, uint32_t ringw_u32,
                          float* __restrict__ hOut, float& c_st, int ub,
                          unsigned base, unsigned w0t, unsigned w1t)
{
    const int tid = threadIdx.x;
    const int w = tid >> 5, l = tid & 31;
    const int ws = w & 7, bh = w >> 3;
    const int bq = l >> 1, gg = l & 1;
    const int bhOff = bh * 64;                 // float offset into each 128-b row

    ull acc[2][8];
#pragma unroll
    for (int j = 0; j < 2; j++)
#pragma unroll
        for (int cp = 0; cp < 8; cp++) { float z = 0.0f; PACK2(acc[j][cp], z, z); }

#define FMAK(Av, KK)                                                             \
    do {                                                                         \
        const float4* wp = (const float4*)(Wc + (KK) * 16 + gg * 8);             \
        float4 wa = wp[0], wb = wp[1];                                           \
        ull w0,w1,w2,w3,w4,w5,w6,w7;                                             \
        PACK2(w0, wa.x, wa.x); PACK2(w1, wa.y, wa.y);                            \
        PACK2(w2, wa.z, wa.z); PACK2(w3, wa.w, wa.w);                            \
        PACK2(w4, wb.x, wb.x); PACK2(w5, wb.y, wb.y);                            \
        PACK2(w6, wb.z, wb.z); PACK2(w7, wb.w, wb.w);                            \
        FMA2(acc[0][0], (Av).x, w0); FMA2(acc[0][1], (Av).x, w1);                \
        FMA2(acc[0][2], (Av).x, w2); FMA2(acc[0][3], (Av).x, w3);                \
        FMA2(acc[0][4], (Av).x, w4); FMA2(acc[0][5], (Av).x, w5);                \
        FMA2(acc[0][6], (Av).x, w6); FMA2(acc[0][7], (Av).x, w7);                \
        FMA2(acc[1][0], (Av).y, w0); FMA2(acc[1][1], (Av).y, w1);                \
        FMA2(acc[1][2], (Av).y, w2); FMA2(acc[1][3], (Av).y, w3);                \
        FMA2(acc[1][4], (Av).y, w4); FMA2(acc[1][5], (Av).y, w5);                \
        FMA2(acc[1][6], (Av).y, w6); FMA2(acc[1][7], (Av).y, w7);                \
    } while (0)

    // cp.async-pipelined segment: 4-row groups, private 3-slot ring, prefetch 2.
#define SEGLOOP(BASE, OFS, S0, S1)                                               \
    do {                                                                         \
        int s0_ = (S0), s1_ = (S1);                                              \
        if (s1_ > s0_) {                                                         \
            const float* bp_ = (BASE) - (size_t)(OFS) * BB;                      \
            const int ng = (s1_ - s0_) >> 2;                                     \
            stage_group(ringw_u32, bp_ + (size_t)s0_ * BB, l, bhOff);            \
            if (ng > 1) stage_group(ringw_u32 + 1024u, bp_ + (size_t)(s0_ + 4) * BB, l, bhOff); \
            for (int g = 0; g < ng; g++) {                                       \
                if (g + 2 < ng) {                                                \
                    int slot = (g + 2) % 3;                                      \
                    stage_group(ringw_u32 + (uint32_t)slot * 1024u,              \
                                bp_ + (size_t)(s0_ + (g + 2) * 4) * BB, l, bhOff);\
                    CPW(2);                                                      \
                } else if (g + 1 < ng) {                                         \
                    CPW(1);                                                      \
                } else {                                                         \
                    CPW(0);                                                      \
                }                                                                \
                SYNCWARP();                                                      \
                const float* sl = ringw + (size_t)(g % 3) * 256 + bq * 4;        \
                _Pragma("unroll")                                                \
                for (int r = 0; r < 4; r++) {                                    \
                    ulonglong2 Av = ((const ulonglong2*)(sl + r * 64))[0];       \
                    FMAK(Av, s0_ + g * 4 + r);                                   \
                }                                                                \
                SYNCWARP();                                                      \
            }                                                                    \
        }                                                                        \
    } while (0)

    // seg0 (ready): optional cheap wait, then compute
    if (w0t) wait_grid(base, w0t);
    {
        const int lw = len0 >> 3;
        const int a0 = kb0 + ws * lw;
        SEGLOOP(s0, kb0, a0, a0 + lw);
    }
    // pending segment: the expensive wait, overlapped by seg0 compute above
    wait_grid(base, w1t);
    {
        const int lw = len1 >> 3;
        const int a0 = kb1 + ws * lw;
        SEGLOOP(s1, kb1, a0, a0 + lw);
    }
#undef SEGLOOP
#undef FMAK

    // split-K-8 reduction (per batch-half): red[(w*32+l)*17 + j*8+cp] (ull, padded)
    {
        ull* rp = red + (size_t)(w * 32 + l) * 17;
#pragma unroll
        for (int j = 0; j < 2; j++)
#pragma unroll
            for (int cp = 0; cp < 8; cp++)
                rp[j * 8 + cp] = acc[j][cp];
    }
    __syncthreads();

    // gather + cell update: thread t = (ul = t>>7, b = t&127), one cell each
    const float* redf = (const float*)red;
    const int b = tid & 127;
    const int ul = tid >> 7;
    const int bhg = b >> 6, bb = b & 63;
    const int bqg = bb >> 2, jg = (bb >> 1) & 1, half = bb & 1;
    float g4[4];
#pragma unroll
    for (int gt = 0; gt < 4; gt++) {
        const int c = ul * 4 + gt;
        const int ggc = c >> 3, cp = c & 7;
        const int lane = bqg * 2 + ggc;
        float s = bias_s[c];
#pragma unroll
        for (int ws2 = 0; ws2 < 8; ws2++) {
            int w2 = bhg * 8 + ws2;
            s += redf[(((size_t)(w2 * 32 + lane) * 17 + jg * 8 + cp) << 1) + half];
        }
        g4[gt] = s;
    }
    float cn = sigf(g4[1]) * c_st + sigf(g4[0]) * tanhf_(g4[2]);
    c_st = cn;
    hOut[(size_t)(ub + ul) * BB + b] = sigf(g4[3]) * tanhf_(cn);
    __syncthreads();
}

// pred[b, icol] = h1[b,:] . wlin (h1 transposed [u][b]); waits for h1 internally
__device__ void pred_step(const float* __restrict__ h1T, const float* __restrict__ wlin_s,
                          float* __restrict__ redf,
                          int t, float* __restrict__ out, int icol,
                          unsigned base, unsigned wt)
{
    wait_grid(base, wt);
    const int tid = threadIdx.x;
    const int b = tid >> 2, q = tid & 3;
    const float* hp = h1T + (size_t)(q * 128) * BB + b;
    const float* wl = wlin_s + q * 128;
    float acc = 0.0f;
#pragma unroll 8
    for (int u = 0; u < 128; u++)
        acc += hp[(size_t)u * BB] * wl[u];
    __syncthreads();
    if (q) redf[(q - 1) * 128 + b] = acc;
    __syncthreads();
    if (!q) {
        float pr = acc + redf[b] + redf[128 + b] + redf[256 + b];
        out[((size_t)b * SS + t) * II + icol] = pr;
        g_decT[icol * BB + b] = pr;
    }
    __syncthreads();
}

// x[b][t][i] -> xT[t][i][b]
__global__ void transpose_x(const float* __restrict__ x)
{
    __shared__ float tile[32][33];
    int t = blockIdx.x;
    int i0 = blockIdx.y * 32, b0 = blockIdx.z * 32;
    int tx = threadIdx.x, ty = threadIdx.y;
#pragma unroll
    for (int j = 0; j < 32; j += 8)
        tile[ty + j][tx] = x[((size_t)(b0 + ty + j) * SS + t) * II + i0 + tx];
    __syncthreads();
#pragma unroll
    for (int j = 0; j < 32; j += 8)
        g_xT[((size_t)t * II + i0 + ty + j) * BB + b0 + tx] = tile[tx][ty + j];
}

__global__ void __launch_bounds__(NTH, 1)
lstm_ae_kernel(const float* Wih_en0, const float* Whh_en0, const float* bih_en0, const float* bhh_en0,
               const float* Wih_en1, const float* Whh_en1, const float* bih_en1, const float* bhh_en1,
               const float* Wih_de0, const float* Whh_de0, const float* bih_de0, const float* bhh_de0,
               const float* Wih_de1, const float* Whh_de1, const float* bih_de1, const float* bhh_de1,
               const float* Wlin,
               float* __restrict__ out)
{
    extern __shared__ float sm[];
    float* Wc1    = sm;                        // 16384 f32 (K=1024 layer)
    float* Wc0    = Wc1 + 16384;               // 10240 f32 (K=640 layer)
    ull*   red    = (ull*)(Wc0 + 10240);       // 512*17 ull = 69632 B
    float* ring   = (float*)(red + 512 * 17);  // 16 warps * 3 slots * 256 f32 = 48KB
    float* wlin_s = ring + 12288;              // 512
    float* bias0  = wlin_s + 512;              // 16
    float* bias1  = bias0 + 16;                // 16

    const int tid = threadIdx.x;
    const int u0  = blockIdx.x * 4;
    const int w   = tid >> 5;

    float* ringw = ring + (size_t)w * 768;     // private 3 x 256-f32 slots
    uint32_t ringw_u32;
    {
        uint32_t b32;
        asm("{ .reg .u64 t; cvta.to.shared.u64 t, %1; cvt.u32.u64 %0, t; }" : "=r"(b32) : "l"(ringw));
        ringw_u32 = b32;
    }

    __shared__ unsigned s_base;
    if (tid == 0) s_base = atomicAdd(&g_release, 0u);

    // zero initial states + decoder feedback
    {
        int g = blockIdx.x * NTH + tid;        // 0..65535
        g_h0T[0][g] = 0.0f; g_h1T[0][g] = 0.0f;
        if (g < II * BB) g_decT[g] = 0.0f;
    }

    load_layer_weights(Wc0, bias0, II, Wih_en0, Whh_en0, bih_en0, bhh_en0, u0);
    load_layer_weights(Wc1, bias1, HH, Wih_en1, Whh_en1, bih_en1, bhh_en1, u0);
    __syncthreads();

    unsigned base = s_base;
    arrive_grid();
    unsigned ns = 1;                           // arrives issued so far
    wait_grid(base, ns);                       // init visible everywhere

    float c0 = 0.0f, c1 = 0.0f;   // one (unit,batch) cell state per thread

    int p = 0;
    // ---- encoder ----
    for (int t = 0; t < SS; t++) {
        // L0: seg0 = x (static), seg1 = h0[t-1] (pending barrier ns)
        lstm_step(g_xT + (size_t)t * II * BB, 0, II,
                  g_h0T[p], II, HH,
                  Wc0, bias0, red, ringw, ringw_u32, g_h0T[p ^ 1], c0, u0,
                  base, 0u, ns);
        arrive_grid(); ns++;
        // L1: seg0 = h1[t-1] (released at ns-1), seg1 = h0[t] (pending ns)
        lstm_step(g_h1T[p], HH, HH,
                  g_h0T[p ^ 1], 0, HH,
                  Wc1, bias1, red, ringw, ringw_u32, g_h1T[p ^ 1], c1, u0,
                  base, ns - 1, ns);
        arrive_grid(); ns++;
        p ^= 1;
    }

    // ---- swap to decoder weights (CTA-local; no grid sync needed) ----
    load_layer_weights(Wc0, bias0, II, Wih_de0, Whh_de0, bih_de0, bhh_de0, u0);
    load_layer_weights(Wc1, bias1, HH, Wih_de1, Whh_de1, bih_de1, bhh_de1, u0);
    for (int k = tid; k < HH; k += NTH) wlin_s[k] = Wlin[blockIdx.x * HH + k];
    __syncthreads();

    // ---- decoder (closed loop) ----
    for (int t = 0; t < SS; t++) {
        // L0: seg0 = h0[t-1] (ready: covered by earlier waits), seg1 = dec (pred[t-1], ns)
        lstm_step(g_h0T[p], II, HH,
                  g_decT, 0, II,
                  Wc0, bias0, red, ringw, ringw_u32, g_h0T[p ^ 1], c0, u0,
                  base, (ns >= 2 ? ns - 2 : 1u), ns);
        arrive_grid(); ns++;
        // L1: seg0 = h1[t-1] (ready), seg1 = h0[t] (pending ns)
        lstm_step(g_h1T[p], HH, HH,
                  g_h0T[p ^ 1], 0, HH,
                  Wc1, bias1, red, ringw, ringw_u32, g_h1T[p ^ 1], c1, u0,
                  base, (ns >= 2 ? ns - 2 : 1u), ns);
        arrive_grid(); ns++;
        // pred: consumes h1[t] (pending ns)
        pred_step(g_h1T[p ^ 1], wlin_s, (float*)red, t, out, blockIdx.x, base, ns);
        arrive_grid(); ns++;
        p ^= 1;
    }
}

extern "C" void kernel_launch(void* const* d_in, const int* in_sizes, int n_in,
                              void* d_out, int out_size)
{
    const float* p[18];
    for (int i = 0; i < 18; i++) p[i] = (const float*)d_in[i];

    transpose_x<<<dim3(SS, II / 32, BB / 32), dim3(32, 8)>>>(p[0]);

    // 106496 + 69632 + 49152 + 2048 + 128 = 227456 B
    const size_t shmem = (16384 + 10240) * 4 + 512 * 17 * 8 + (12288 + 512 + 16 + 16) * 4;
    cudaFuncSetAttribute(lstm_ae_kernel, cudaFuncAttributeMaxDynamicSharedMemorySize, (int)shmem);

    lstm_ae_kernel<<<GRIDX, NTH, shmem>>>(
        p[1], p[2], p[3], p[4],
        p[5], p[6], p[7], p[8],
        p[9], p[10], p[11], p[12],
        p[13], p[14], p[15], p[16],
        p[17],
        (float*)d_out);
}